// round 5
// baseline (speedup 1.0000x reference)
#include <cuda_runtime.h>

// NeuralCRF log-partition backward DP, one CTA per batch (B=64), 256 threads.
// Beta_i = m + log( sum_j exp(trans_ij) * exp(em_j + Beta_j - m) ).
// Row split: threads 2i and 2i+1 each own HALF of E row i (64 fp32 regs),
// compute 64-FMA partials, combine with shfl_xor(1) (same warp). 2 warps per
// SMSP hide the serial latency (BAR/LDS/log/exp) under the partner warp's
// FMA issue. Shift m is 2-executed-steps stale (thread 0 writes it for step
// t+2; the step-t+1 barrier publishes it) -> exactly ONE __syncthreads per
// step; u double-buffered by parity. Exponent range with stale shift stays
// ~[-6,+11]: fp32-safe. Exact block logsumexp only at the very end.

#define TDIM 128
#define NTHR 256

__global__ __launch_bounds__(NTHR, 1)
void crf_logz_kernel(const int* __restrict__ W,
                     const float* __restrict__ em,
                     const float* __restrict__ trans,
                     float* __restrict__ out,
                     int S)
{
    const int b   = blockIdx.x;
    const int tid = threadIdx.x;
    const int row = tid >> 1;     // output row this pair owns
    const int h   = tid & 1;      // which half of the contraction

    __shared__ __align__(16) float u_sm[2][TDIM];
    __shared__ float m_sm[2];
    __shared__ float red_sm[16];

    // ---- E half-row: e[j] = exp(trans[row, 64h + j]), j = 0..63 ----
    float e[64];
    {
        const float4* trow =
            reinterpret_cast<const float4*>(trans + row * TDIM + h * 64);
#pragma unroll
        for (int j4 = 0; j4 < 16; ++j4) {
            float4 t4 = __ldg(trow + j4);
            e[4 * j4 + 0] = __expf(t4.x);
            e[4 * j4 + 1] = __expf(t4.y);
            e[4 * j4 + 2] = __expf(t4.z);
            e[4 * j4 + 3] = __expf(t4.w);
        }
    }
    const float trans_bot = __ldg(trans + 1 * TDIM + row);  // trans[BOT=1,row]

    const float* emb = em + (size_t)b * (size_t)S * TDIM;
    const int*   Wb  = W  + (size_t)b * (size_t)S;

    float Beta = 0.0f;
    if (tid == 0) { m_sm[0] = 3.5f; m_sm[1] = 11.0f; }

    // distance-2 prefetch of emission element (this row) + word id
    float eA = emb[(size_t)(S - 1) * TDIM + row];
    float eB = emb[(size_t)(S - 2) * TDIM + row];
    int   wA = Wb[S - 1];
    int   wB = Wb[S - 2];

    int p = 0;  // parity over EXECUTED steps
    __syncthreads();

    for (int r = S - 1; r >= 1; --r) {
        int rp = r - 2;
        rp = rp < 0 ? 0 : rp;               // r==1 prefetches row 0 (final)
        float eC = emb[(size_t)rp * TDIM + row];
        int   wC = Wb[rp];

        if ((wA != 0) & (wA != 3)) {        // mask, uniform across block
            float m = m_sm[p];              // written 2 executed steps ago
            if (h == 0)
                u_sm[p][row] = __expf(eA + Beta - m);
            __syncthreads();                // the ONLY barrier per step

            float a0 = 0.f, a1 = 0.f, a2 = 0.f, a3 = 0.f;
            float a4 = 0.f, a5 = 0.f, a6 = 0.f, a7 = 0.f;
            const float4* u4p =
                reinterpret_cast<const float4*>(u_sm[p] + h * 64);
#pragma unroll
            for (int k = 0; k < 16; ++k) {  // 16 x LDS.128 (2 bcast addrs/warp)
                float4 uv = u4p[k];
                if (k & 1) {
                    a4 = fmaf(e[4 * k + 0], uv.x, a4);
                    a5 = fmaf(e[4 * k + 1], uv.y, a5);
                    a6 = fmaf(e[4 * k + 2], uv.z, a6);
                    a7 = fmaf(e[4 * k + 3], uv.w, a7);
                } else {
                    a0 = fmaf(e[4 * k + 0], uv.x, a0);
                    a1 = fmaf(e[4 * k + 1], uv.y, a1);
                    a2 = fmaf(e[4 * k + 2], uv.z, a2);
                    a3 = fmaf(e[4 * k + 3], uv.w, a3);
                }
            }
            float partial = ((a0 + a1) + (a2 + a3)) + ((a4 + a5) + (a6 + a7));
            float total = partial + __shfl_xor_sync(0xffffffffu, partial, 1);

            if (h == 0) {
                Beta = m + __logf(total);
                if (tid == 0) m_sm[p] = Beta + 8.0f;  // shift for step t+2
            }
            p ^= 1;
        }

        eA = eB; wA = wB;
        eB = eC; wB = wC;
    }

    // ---- logZ = lse_row( trans[BOT,row] + em[b,0,row] + Beta_row ), exact.
    // eA now holds emissions[b, 0, row]; only h==0 lanes carry valid Beta.
    float f = (h == 0) ? (trans_bot + eA + Beta) : -INFINITY;

    float mv = f;
#pragma unroll
    for (int o = 16; o > 0; o >>= 1)
        mv = fmaxf(mv, __shfl_xor_sync(0xffffffffu, mv, o));
    if ((tid & 31) == 0) red_sm[tid >> 5] = mv;
    __syncthreads();
    float mm = red_sm[0];
#pragma unroll
    for (int w = 1; w < NTHR / 32; ++w) mm = fmaxf(mm, red_sm[w]);

    float s = __expf(f - mm);                // exp(-inf) = 0 for h==1 lanes
#pragma unroll
    for (int o = 16; o > 0; o >>= 1)
        s += __shfl_xor_sync(0xffffffffu, s, o);
    if ((tid & 31) == 0) red_sm[8 + (tid >> 5)] = s;
    __syncthreads();

    if (tid == 0) {
        float tot = 0.f;
#pragma unroll
        for (int w = 0; w < NTHR / 32; ++w) tot += red_sm[8 + w];
        out[b] = mm + __logf(tot);
    }
}

extern "C" void kernel_launch(void* const* d_in, const int* in_sizes, int n_in,
                              void* d_out, int out_size)
{
    const int*   W     = (const int*)d_in[0];
    const float* em    = (const float*)d_in[1];
    const float* trans = (const float*)d_in[2];
    float*       out   = (float*)d_out;

    const int B = out_size;            // 64
    const int S = in_sizes[0] / B;     // 1024

    crf_logz_kernel<<<B, NTHR>>>(W, em, trans, out, S);
}

// round 6
// speedup vs baseline: 1.3383x; 1.3383x over previous
#include <cuda_runtime.h>

// NeuralCRF log-partition backward DP, one CTA per batch (B=64), 128 threads.
// Raw-state formulation: thread i keeps t_i (the raw matvec sum); the true
// state is Beta_i = m_k + log t_i, but log/exp NEVER appear on the serial
// critical path:
//     u_i(step k) = t_i * exA * edN
// where exA = exp(em) is computed at prefetch time (2 rows early) and
// edN = exp(m_{k-1} - m_k) is a scalar published by thread 0 two executed
// steps in advance (visible via the existing single per-step barrier, loaded
// into a register right after the PREVIOUS step's barrier). Thread 0 runs the
// m-chain (log t0, exp(dm)) entirely off-path. One __syncthreads per step;
// u double-buffered by parity. Exponents stay ~[-6.5, +6.5]: fp32-safe.
// Exact block logsumexp only at the very end.

#define TDIM 128

__global__ __launch_bounds__(TDIM, 1)
void crf_logz_kernel(const int* __restrict__ W,
                     const float* __restrict__ em,
                     const float* __restrict__ trans,
                     float* __restrict__ out,
                     int S)
{
    const int b = blockIdx.x;
    const int i = threadIdx.x;

    __shared__ __align__(16) float u_sm[2][TDIM];
    __shared__ float ed_sm[2];     // exp(m_{k-1} - m_k), published 2 steps early
    __shared__ float mfin_sm;      // m of the last executed step
    __shared__ float red_sm[8];

    // ---- E row i = exp(trans[i,:]) in 128 registers (one-time) ----
    float e[TDIM];
    {
        const float4* trow = reinterpret_cast<const float4*>(trans + i * TDIM);
#pragma unroll
        for (int j4 = 0; j4 < TDIM / 4; ++j4) {
            float4 t4 = __ldg(trow + j4);
            e[4 * j4 + 0] = __expf(t4.x);
            e[4 * j4 + 1] = __expf(t4.y);
            e[4 * j4 + 2] = __expf(t4.z);
            e[4 * j4 + 3] = __expf(t4.w);
        }
    }
    const float trans_bot = __ldg(trans + 1 * TDIM + i);  // trans[BOT=1, i]

    const float* emb = em + (size_t)b * (size_t)S * TDIM;
    const int*   Wb  = W  + (size_t)b * (size_t)S;

    // State: t_i = exp(Beta_i - m_k); init Beta=0, m_0=0 -> t=1.
    float t = 1.0f;
    float edN = 1.0f;              // expD for the NEXT executed step (k=0): 1

    // Thread-0 m-chain regs: m_k and m_{k+1}. m_0=0; m_1 ~= one-step growth.
    float m0r = 0.0f, m1r = 5.35f;
    if (i == 0) {
        ed_sm[1] = __expf(0.0f - 5.35f);  // expD_1 = exp(m_0 - m_1)
        ed_sm[0] = 1.0f;                  // overwritten at k=0 before any read
        mfin_sm  = 0.0f;                  // if no step executes
    }

    // distance-2 prefetch of emission element (+ its exp) and word id
    float eA = emb[(size_t)(S - 1) * TDIM + i];
    float eB = emb[(size_t)(S - 2) * TDIM + i];
    float exA = __expf(eA);
    float exB = __expf(eB);
    int   wA = Wb[S - 1];
    int   wB = Wb[S - 2];

    float m_used = 0.0f;           // thread 0: m_k of last executed step
    int p = 0;                     // parity over EXECUTED steps
    __syncthreads();

    for (int r = S - 1; r >= 1; --r) {
        int rp = r - 2;
        rp = rp < 0 ? 0 : rp;                 // r==1 prefetches row 0 (final)
        float eC = emb[(size_t)rp * TDIM + i];
        int   wC = Wb[rp];
        float exC = __expf(eC);               // off-path (2 rows early)

        if ((wA != 0) & (wA != 3)) {          // mask, uniform across block
            u_sm[p][i] = t * (exA * edN);     // 2 FMULs -> STS (no MUFU!)
            __syncthreads();                  // the ONLY barrier per step

            // expD for the NEXT executed step (published >= 1 step ago)
            edN = ed_sm[p ^ 1];

            float a0 = 0.f, a1 = 0.f, a2 = 0.f, a3 = 0.f;
            const float4* u4p = reinterpret_cast<const float4*>(u_sm[p]);
#pragma unroll
            for (int k = 0; k < TDIM / 4; ++k) {   // 32 x LDS.128 broadcast
                float4 uv = u4p[k];
                a0 = fmaf(e[4 * k + 0], uv.x, a0);
                a1 = fmaf(e[4 * k + 1], uv.y, a1);
                a2 = fmaf(e[4 * k + 2], uv.z, a2);
                a3 = fmaf(e[4 * k + 3], uv.w, a3);
            }
            t = (a0 + a1) + (a2 + a3);        // new raw state; NO log here

            if (i == 0) {
                // off-path m-chain (consumed 2 executed steps later):
                // Beta0_k = m_k + log t0;  m_{k+2} = Beta0_k + 5.5
                float mk2 = m0r + __logf(t) + 5.5f;
                ed_sm[p] = __expf(m1r - mk2); // expD_{k+2}
                m_used = m0r;                 // m of THIS step
                m0r = m1r;
                m1r = mk2;
            }
            p ^= 1;
        }

        eA = eB;  exA = exB;  wA = wB;
        eB = eC;  exB = exC;  wB = wC;
    }

    if (i == 0) mfin_sm = m_used;
    __syncthreads();
    const float mfin = mfin_sm;

    // ---- logZ = lse_i( trans[BOT,i] + em[b,0,i] + mfin + log t_i ), exact.
    // eA now holds emissions[b, 0, i].
    float f = trans_bot + eA + mfin + __logf(t);

    float mv = f;
#pragma unroll
    for (int o = 16; o > 0; o >>= 1)
        mv = fmaxf(mv, __shfl_xor_sync(0xffffffffu, mv, o));
    if ((i & 31) == 0) red_sm[i >> 5] = mv;
    __syncthreads();
    float mm = fmaxf(fmaxf(red_sm[0], red_sm[1]), fmaxf(red_sm[2], red_sm[3]));

    float s = __expf(f - mm);
#pragma unroll
    for (int o = 16; o > 0; o >>= 1)
        s += __shfl_xor_sync(0xffffffffu, s, o);
    if ((i & 31) == 0) red_sm[4 + (i >> 5)] = s;
    __syncthreads();

    if (i == 0) {
        float tot = (red_sm[4] + red_sm[5]) + (red_sm[6] + red_sm[7]);
        out[b] = mm + __logf(tot);
    }
}

extern "C" void kernel_launch(void* const* d_in, const int* in_sizes, int n_in,
                              void* d_out, int out_size)
{
    const int*   W     = (const int*)d_in[0];
    const float* em    = (const float*)d_in[1];
    const float* trans = (const float*)d_in[2];
    float*       out   = (float*)d_out;

    const int B = out_size;            // 64
    const int S = in_sizes[0] / B;     // 1024

    crf_logz_kernel<<<B, TDIM>>>(W, em, trans, out, S);
}

// round 7
// speedup vs baseline: 1.4071x; 1.0515x over previous
#include <cuda_runtime.h>

// NeuralCRF log-partition backward DP. TWO independent batch chains per CTA:
// threads [0,128) run batch 2*blk, threads [128,256) run batch 2*blk+1.
// Each chain is the proven single-chain loop (row-per-thread, exp(trans)
// register-resident, ONE barrier per step, 2-executed-step-stale shift m),
// synced with NAMED barriers so the chains never couple (their masks differ).
// Two warps per SMSP from independent chains: one chain's serial-latency tail
// (BAR release, LDS, acc tree, log/exp) is filled by the other chain's FMA
// issue. Exact block logsumexp only at the end.

#define TDIM 128

__global__ __launch_bounds__(256, 1)
void crf_logz_kernel(const int* __restrict__ W,
                     const float* __restrict__ em,
                     const float* __restrict__ trans,
                     float* __restrict__ out,
                     int S)
{
    const int chain = threadIdx.x >> 7;       // 0 or 1
    const int i     = threadIdx.x & 127;      // row within chain
    const int b     = blockIdx.x * 2 + chain; // batch element
    const int barid = 1 + chain;              // named barrier per chain

#define CBAR() asm volatile("bar.sync %0, 128;" :: "r"(barid) : "memory")

    __shared__ __align__(16) float u_sm[2][2][TDIM];  // [chain][parity][j]
    __shared__ float m_sm[2][2];                      // [chain][parity]
    __shared__ float red_sm[2][8];                    // [chain][...]

    // ---- E row i = exp(trans[i,:]) in 128 registers (one-time) ----
    float e[TDIM];
    {
        const float4* trow = reinterpret_cast<const float4*>(trans + i * TDIM);
#pragma unroll
        for (int j4 = 0; j4 < TDIM / 4; ++j4) {
            float4 t4 = __ldg(trow + j4);
            e[4 * j4 + 0] = __expf(t4.x);
            e[4 * j4 + 1] = __expf(t4.y);
            e[4 * j4 + 2] = __expf(t4.z);
            e[4 * j4 + 3] = __expf(t4.w);
        }
    }
    const float trans_bot = __ldg(trans + 1 * TDIM + i);  // trans[BOT=1, i]

    const float* emb = em + (size_t)b * (size_t)S * TDIM;
    const int*   Wb  = W  + (size_t)b * (size_t)S;

    float Beta = 0.0f;
    if (i == 0) { m_sm[chain][0] = 3.5f; m_sm[chain][1] = 11.0f; }

    // distance-2 prefetch of emission element (this row) + word id
    float eA = emb[(size_t)(S - 1) * TDIM + i];
    float eB = emb[(size_t)(S - 2) * TDIM + i];
    int   wA = Wb[S - 1];
    int   wB = Wb[S - 2];

    int p = 0;  // parity over EXECUTED steps of THIS chain
    CBAR();

    for (int r = S - 1; r >= 1; --r) {
        int rp = r - 2;
        rp = rp < 0 ? 0 : rp;               // r==1 prefetches row 0 (final)
        float eC = emb[(size_t)rp * TDIM + i];
        int   wC = Wb[rp];

        if ((wA != 0) & (wA != 3)) {        // mask, uniform within the chain
            float m = m_sm[chain][p];       // written 2 executed steps ago
            u_sm[chain][p][i] = __expf(eA + Beta - m);
            CBAR();                         // the ONLY barrier per step

            float a0 = 0.f, a1 = 0.f, a2 = 0.f, a3 = 0.f;
            const float4* u4p =
                reinterpret_cast<const float4*>(u_sm[chain][p]);
#pragma unroll
            for (int k = 0; k < TDIM / 4; ++k) {   // 32 x LDS.128 broadcast
                float4 uv = u4p[k];
                a0 = fmaf(e[4 * k + 0], uv.x, a0);
                a1 = fmaf(e[4 * k + 1], uv.y, a1);
                a2 = fmaf(e[4 * k + 2], uv.z, a2);
                a3 = fmaf(e[4 * k + 3], uv.w, a3);
            }
            Beta = m + __logf((a0 + a1) + (a2 + a3));
            // shift for step t+2 (published by the NEXT step's barrier);
            // exponent stays ~[-3, +9]: fp32-safe.
            if (i == 0) m_sm[chain][p] = Beta + 8.0f;
            p ^= 1;
        }

        eA = eB; wA = wB;
        eB = eC; wB = wC;
    }

    // ---- logZ = lse_i( trans[BOT,i] + em[b,0,i] + Beta_i ), exact ----
    // eA now holds emissions[b, 0, i].
    float f = trans_bot + eA + Beta;

    float mv = f;
#pragma unroll
    for (int o = 16; o > 0; o >>= 1)
        mv = fmaxf(mv, __shfl_xor_sync(0xffffffffu, mv, o));
    if ((i & 31) == 0) red_sm[chain][i >> 5] = mv;
    CBAR();
    float mm = fmaxf(fmaxf(red_sm[chain][0], red_sm[chain][1]),
                     fmaxf(red_sm[chain][2], red_sm[chain][3]));

    float s = __expf(f - mm);
#pragma unroll
    for (int o = 16; o > 0; o >>= 1)
        s += __shfl_xor_sync(0xffffffffu, s, o);
    if ((i & 31) == 0) red_sm[chain][4 + (i >> 5)] = s;
    CBAR();

    if (i == 0) {
        float tot = (red_sm[chain][4] + red_sm[chain][5]) +
                    (red_sm[chain][6] + red_sm[chain][7]);
        out[b] = mm + __logf(tot);
    }
#undef CBAR
}

extern "C" void kernel_launch(void* const* d_in, const int* in_sizes, int n_in,
                              void* d_out, int out_size)
{
    const int*   W     = (const int*)d_in[0];
    const float* em    = (const float*)d_in[1];
    const float* trans = (const float*)d_in[2];
    float*       out   = (float*)d_out;

    const int B = out_size;            // 64
    const int S = in_sizes[0] / B;     // 1024

    crf_logz_kernel<<<B / 2, 256>>>(W, em, trans, out, S);
}

// round 8
// speedup vs baseline: 2.2860x; 1.6246x over previous
#include <cuda_runtime.h>
#include <cuda_fp16.h>

// NeuralCRF log-partition backward DP, one CTA per batch (B=64), 128 threads.
// Beta_i = m + log( sum_j exp(trans_ij) * exp(em_j + Beta_j - m) ).
// The 128-wide contraction runs in fp16x2 via HFMA2: exp(trans) row held as
// 64 half2 registers, u stored in SMEM as fp16 -> 64 HFMA2 (128 issue cyc)
// instead of 128 FFMA (256 cyc). Stale shift m = Beta0(2 executed steps ago)
// + 5.5 keeps u in [3e-3, 225] (fp16-safe, no overflow: sums <= ~600).
// 16 rotating half2 accumulators (4-deep chains) + early switch to fp32 in
// the reduction tree bound the fp16 accumulation error to ~1e-3/step
// (random-walk => ~0.03 abs on logZ ~ 5600). ONE __syncthreads per step;
// u double-buffered by parity. Exact fp32 block logsumexp at the end.

#define TDIM 128

__global__ __launch_bounds__(TDIM, 1)
void crf_logz_kernel(const int* __restrict__ W,
                     const float* __restrict__ em,
                     const float* __restrict__ trans,
                     float* __restrict__ out,
                     int S)
{
    const int b = blockIdx.x;
    const int i = threadIdx.x;

    __shared__ __align__(16) __half u_sm[2][TDIM];
    __shared__ float m_sm[2];
    __shared__ float red_sm[8];

    // ---- E row i = exp(trans[i,:]) as 64 half2 registers (one-time) ----
    __half2 e2[TDIM / 2];
    {
        const float4* trow = reinterpret_cast<const float4*>(trans + i * TDIM);
#pragma unroll
        for (int j4 = 0; j4 < TDIM / 4; ++j4) {
            float4 t4 = __ldg(trow + j4);
            e2[2 * j4 + 0] = __floats2half2_rn(__expf(t4.x), __expf(t4.y));
            e2[2 * j4 + 1] = __floats2half2_rn(__expf(t4.z), __expf(t4.w));
        }
    }
    const float trans_bot = __ldg(trans + 1 * TDIM + i);  // trans[BOT=1, i]

    const float* emb = em + (size_t)b * (size_t)S * TDIM;
    const int*   Wb  = W  + (size_t)b * (size_t)S;

    float Beta = 0.0f;
    // m for 1st executed step: Beta=0, em in +-4.5 -> exp in [3e-4, 2.7].
    // m for 2nd executed step: Beta ~ 5.35 -> exp(em + 5.35 - 9) in [1e-4, 7].
    if (i == 0) { m_sm[0] = 3.5f; m_sm[1] = 9.0f; }

    // distance-2 prefetch of emission element (this row) + word id
    float eA = emb[(size_t)(S - 1) * TDIM + i];
    float eB = emb[(size_t)(S - 2) * TDIM + i];
    int   wA = Wb[S - 1];
    int   wB = Wb[S - 2];

    int p = 0;  // parity over EXECUTED steps
    __syncthreads();

    for (int r = S - 1; r >= 1; --r) {
        int rp = r - 2;
        rp = rp < 0 ? 0 : rp;               // r==1 prefetches row 0 (final)
        float eC = emb[(size_t)rp * TDIM + i];
        int   wC = Wb[rp];

        if ((wA != 0) & (wA != 3)) {        // mask, uniform across block
            float m = m_sm[p];              // written 2 executed steps ago
            u_sm[p][i] = __float2half_rn(__expf(eA + Beta - m));
            __syncthreads();                // the ONLY barrier per step

            __half2 acc[16];
#pragma unroll
            for (int k = 0; k < 16; ++k) acc[k] = __float2half2_rn(0.0f);

            const uint4* u4p = reinterpret_cast<const uint4*>(u_sm[p]);
#pragma unroll
            for (int k = 0; k < 16; ++k) {  // 16 x LDS.128 broadcast
                uint4 w = u4p[k];           // 8 halves = 4 half2
                __half2 h0 = *reinterpret_cast<__half2*>(&w.x);
                __half2 h1 = *reinterpret_cast<__half2*>(&w.y);
                __half2 h2 = *reinterpret_cast<__half2*>(&w.z);
                __half2 h3 = *reinterpret_cast<__half2*>(&w.w);
                int a = (4 * k) & 15;
                acc[a + 0] = __hfma2(e2[4 * k + 0], h0, acc[a + 0]);
                acc[a + 1] = __hfma2(e2[4 * k + 1], h1, acc[a + 1]);
                acc[a + 2] = __hfma2(e2[4 * k + 2], h2, acc[a + 2]);
                acc[a + 3] = __hfma2(e2[4 * k + 3], h3, acc[a + 3]);
            }
            // 16 -> 4 in half2 (magnitudes still ~S/4), then exact fp32 tail
#pragma unroll
            for (int j = 0; j < 8; ++j) acc[j] = __hadd2(acc[j], acc[j + 8]);
#pragma unroll
            for (int j = 0; j < 4; ++j) acc[j] = __hadd2(acc[j], acc[j + 4]);
            float2 f0 = __half22float2(acc[0]);
            float2 f1 = __half22float2(acc[1]);
            float2 f2 = __half22float2(acc[2]);
            float2 f3 = __half22float2(acc[3]);
            float v = ((f0.x + f0.y) + (f1.x + f1.y)) +
                      ((f2.x + f2.y) + (f3.x + f3.y));

            Beta = m + __logf(v);
            // shift for step t+2: one-step expected growth ~5.35 keeps the
            // fp16 u's centered: exp range ~[-5.7, +5.4].
            if (i == 0) m_sm[p] = Beta + 5.5f;
            p ^= 1;
        }

        eA = eB; wA = wB;
        eB = eC; wB = wC;
    }

    // ---- logZ = lse_i( trans[BOT,i] + em[b,0,i] + Beta_i ), exact fp32 ----
    // eA now holds emissions[b, 0, i].
    float f = trans_bot + eA + Beta;

    float mv = f;
#pragma unroll
    for (int o = 16; o > 0; o >>= 1)
        mv = fmaxf(mv, __shfl_xor_sync(0xffffffffu, mv, o));
    if ((i & 31) == 0) red_sm[i >> 5] = mv;
    __syncthreads();
    float mm = fmaxf(fmaxf(red_sm[0], red_sm[1]), fmaxf(red_sm[2], red_sm[3]));

    float s = __expf(f - mm);
#pragma unroll
    for (int o = 16; o > 0; o >>= 1)
        s += __shfl_xor_sync(0xffffffffu, s, o);
    if ((i & 31) == 0) red_sm[4 + (i >> 5)] = s;
    __syncthreads();

    if (i == 0) {
        float tot = (red_sm[4] + red_sm[5]) + (red_sm[6] + red_sm[7]);
        out[b] = mm + __logf(tot);
    }
}

extern "C" void kernel_launch(void* const* d_in, const int* in_sizes, int n_in,
                              void* d_out, int out_size)
{
    const int*   W     = (const int*)d_in[0];
    const float* em    = (const float*)d_in[1];
    const float* trans = (const float*)d_in[2];
    float*       out   = (float*)d_out;

    const int B = out_size;            // 64
    const int S = in_sizes[0] / B;     // 1024

    crf_logz_kernel<<<B, TDIM>>>(W, em, trans, out, S);
}

// round 9
// speedup vs baseline: 2.5520x; 1.1163x over previous
#include <cuda_runtime.h>
#include <cuda_fp16.h>

// NeuralCRF log-partition backward DP, one CTA per batch (B=64), 128 threads.
// Raw-state HFMA2 formulation. Thread i keeps t_i = exp(Beta_i - m_{s-1}).
// Step s: u_j = t_j * pre_j,  pre_j = exp(em_j + Delta_s),
//         t_i = sum_j exp(trans_ij) * u_j   (64 HFMA2, e2 register-resident)
// Delta_s = m_{s-1} - m_s is known a full iteration early (shift schedule m
// is set 2 executed steps ahead from a published t0), so pre is computed
// OFF-PATH during the previous step's FMA phase. No log/exp on the serial
// critical path: tree -> FMUL -> CVT -> STS -> BAR -> LDS -> HFMA2.
// The m-chain is computed redundantly by ALL threads from broadcast t0
// (uniform registers, no divergence, no on-path smem shift read).
// ONE __syncthreads per step; u and t0 double-buffered by parity.
// Exact fp32 block logsumexp at the end.

#define TDIM 128

__global__ __launch_bounds__(TDIM, 1)
void crf_logz_kernel(const int* __restrict__ W,
                     const float* __restrict__ em,
                     const float* __restrict__ trans,
                     float* __restrict__ out,
                     int S)
{
    const int b = blockIdx.x;
    const int i = threadIdx.x;

    __shared__ __align__(16) __half u_sm[2][TDIM];
    __shared__ float t0_sm[2];
    __shared__ float red_sm[8];

    // ---- E row i = exp(trans[i,:]) as 64 half2 registers (one-time) ----
    __half2 e2[TDIM / 2];
    {
        const float4* trow = reinterpret_cast<const float4*>(trans + i * TDIM);
#pragma unroll
        for (int j4 = 0; j4 < TDIM / 4; ++j4) {
            float4 t4 = __ldg(trow + j4);
            e2[2 * j4 + 0] = __floats2half2_rn(__expf(t4.x), __expf(t4.y));
            e2[2 * j4 + 1] = __floats2half2_rn(__expf(t4.z), __expf(t4.w));
        }
    }
    const float trans_bot = __ldg(trans + 1 * TDIM + i);  // trans[BOT=1, i]

    const float* emb = em + (size_t)b * (size_t)S * TDIM;
    const int*   Wb  = W  + (size_t)b * (size_t)S;

    // Raw state: t = exp(Beta - m_prev); init Beta=0, m_{-1}=0 -> t=1.
    float t = 1.0f;
    // Shift schedule (uniform registers): m_prev=m_{-1}, m_cur=m_0, m_nxt=m_1.
    float m_prev = 0.0f, m_cur = 3.5f, m_nxt = 9.0f;
    float dN = m_prev - m_cur;               // Delta of next executed step

    if (i == 0) { t0_sm[0] = 1.0f; t0_sm[1] = 1.0f; }

    // distance-2 prefetch of emission element (this row) + word id
    float eA = emb[(size_t)(S - 1) * TDIM + i];
    float eB = emb[(size_t)(S - 2) * TDIM + i];
    int   wA = Wb[S - 1];
    int   wB = Wb[S - 2];

    float preA = __expf(eA + dN);  // pre for row S-1 (if executed: step 0)
    float preB = 0.0f;             // becomes valid at end of first iteration

    int p = 0;  // parity over EXECUTED steps
    __syncthreads();

    for (int r = S - 1; r >= 1; --r) {
        int rp = r - 2;
        rp = rp < 0 ? 0 : rp;               // r==1 prefetches row 0 (final)
        float eC = emb[(size_t)rp * TDIM + i];
        int   wC = Wb[rp];

        if ((wA != 0) & (wA != 3)) {        // mask, uniform across block
            // ---- ON-PATH: u = t * pre (no MUFU), cvt, STS, barrier ----
            u_sm[p][i] = __float2half_rn(t * preA);
            __syncthreads();                // the ONLY barrier per step

            // broadcast t0 of the PREVIOUS executed step (off-path)
            float T0 = t0_sm[p ^ 1];

            __half2 acc[16];
#pragma unroll
            for (int k = 0; k < 16; ++k) acc[k] = __float2half2_rn(0.0f);

            const uint4* u4p = reinterpret_cast<const uint4*>(u_sm[p]);
#pragma unroll
            for (int k = 0; k < 16; ++k) {  // 16 x LDS.128 broadcast
                uint4 w = u4p[k];           // 8 halves = 4 half2
                __half2 h0 = *reinterpret_cast<__half2*>(&w.x);
                __half2 h1 = *reinterpret_cast<__half2*>(&w.y);
                __half2 h2 = *reinterpret_cast<__half2*>(&w.z);
                __half2 h3 = *reinterpret_cast<__half2*>(&w.w);
                acc[4 * k & 15]       = __hfma2(e2[4 * k + 0], h0, acc[4 * k & 15]);
                acc[(4 * k + 1) & 15] = __hfma2(e2[4 * k + 1], h1, acc[(4 * k + 1) & 15]);
                acc[(4 * k + 2) & 15] = __hfma2(e2[4 * k + 2], h2, acc[(4 * k + 2) & 15]);
                acc[(4 * k + 3) & 15] = __hfma2(e2[4 * k + 3], h3, acc[(4 * k + 3) & 15]);
            }
#pragma unroll
            for (int j = 0; j < 8; ++j) acc[j] = __hadd2(acc[j], acc[j + 8]);
#pragma unroll
            for (int j = 0; j < 4; ++j) acc[j] = __hadd2(acc[j], acc[j + 4]);
            float2 f0 = __half22float2(acc[0]);
            float2 f1 = __half22float2(acc[1]);
            float2 f2 = __half22float2(acc[2]);
            float2 f3 = __half22float2(acc[3]);
            t = ((f0.x + f0.y) + (f1.x + f1.y)) +
                ((f2.x + f2.y) + (f3.x + f3.y));   // new raw state (fp32)

            if (i == 0) t0_sm[p] = t;       // publish for step k+1 (off-path)

            // ---- OFF-PATH scalar m-chain (uniform across all threads) ----
            // Beta0 of step k-1 = m_{k-1} + log T0; m_{k+2} = that + 10.85
            // (3 steps of expected growth ~3*5.35 + ~0.15 headroom).
            float m_new = m_prev + __logf(T0) + 10.85f;
            m_prev = m_cur;                 // m_k   (m of THIS step)
            m_cur  = m_nxt;                 // m_{k+1}
            m_nxt  = m_new;                 // m_{k+2}
            dN = m_prev - m_cur;            // Delta_{k+1}
            p ^= 1;
        }

        // pre for row r-1, consumed next iteration (off-path MUFU)
        preB = __expf(eB + dN);

        eA = eB;  preA = preB;  wA = wB;
        eB = eC;  wB = wC;
    }

    // ---- logZ = lse_i( trans[BOT,i] + em[b,0,i] + m_last + log t_i ) ----
    // eA holds emissions[b,0,i]; m_prev = m of the last executed step.
    float f = trans_bot + eA + m_prev + __logf(t);

    float mv = f;
#pragma unroll
    for (int o = 16; o > 0; o >>= 1)
        mv = fmaxf(mv, __shfl_xor_sync(0xffffffffu, mv, o));
    if ((i & 31) == 0) red_sm[i >> 5] = mv;
    __syncthreads();
    float mm = fmaxf(fmaxf(red_sm[0], red_sm[1]), fmaxf(red_sm[2], red_sm[3]));

    float s = __expf(f - mm);
#pragma unroll
    for (int o = 16; o > 0; o >>= 1)
        s += __shfl_xor_sync(0xffffffffu, s, o);
    if ((i & 31) == 0) red_sm[4 + (i >> 5)] = s;
    __syncthreads();

    if (i == 0) {
        float tot = (red_sm[4] + red_sm[5]) + (red_sm[6] + red_sm[7]);
        out[b] = mm + __logf(tot);
    }
}

extern "C" void kernel_launch(void* const* d_in, const int* in_sizes, int n_in,
                              void* d_out, int out_size)
{
    const int*   W     = (const int*)d_in[0];
    const float* em    = (const float*)d_in[1];
    const float* trans = (const float*)d_in[2];
    float*       out   = (float*)d_out;

    const int B = out_size;            // 64
    const int S = in_sizes[0] / B;     // 1024

    crf_logz_kernel<<<B, TDIM>>>(W, em, trans, out, S);
}

// round 10
// speedup vs baseline: 2.6632x; 1.0436x over previous
#include <cuda_runtime.h>
#include <cuda_fp16.h>

// NeuralCRF log-partition backward DP, one CTA per batch (B=64), 128 threads.
// All-fp16 serial spine. Thread i keeps t_h = exp(Beta_i - m_{s-1}) in HALF.
// Step s: u_j = t_j * pre_j (HMUL, pre_j = exp(em_j + Delta_s) as half,
// computed OFF-PATH a full iteration early from the predetermined shift
// schedule), then t_i = sum_j exp(trans_ij) * u_j via 64 HFMA2 into 8
// rotating half2 accumulators, 3-level HADD2 tree, fold to scalar half.
// NO fp32<->fp16 conversions and NO MUFU on the serial critical path:
// tree -> HMUL -> STS.16 -> BAR -> LDS -> HFMA2. The scalar m-chain runs
// redundantly on all threads from a broadcast t0 (fp32, off-path).
// ONE __syncthreads per step; u/t0 double-buffered by executed-parity.
// W preloaded to SMEM. Exact fp32 block logsumexp at the end.

#define TDIM 128

__global__ __launch_bounds__(TDIM, 1)
void crf_logz_kernel(const int* __restrict__ W,
                     const float* __restrict__ em,
                     const float* __restrict__ trans,
                     float* __restrict__ out,
                     int S)
{
    const int b = blockIdx.x;
    const int i = threadIdx.x;

    extern __shared__ int smem_dyn[];
    int* w_sm = smem_dyn;                      // S ints (word ids)
    __shared__ __align__(16) __half u_sm[2][TDIM];
    __shared__ float t0_sm[2];
    __shared__ float red_sm[8];

    // ---- E row i = exp(trans[i,:]) as 64 half2 registers (one-time) ----
    __half2 e2[TDIM / 2];
    {
        const float4* trow = reinterpret_cast<const float4*>(trans + i * TDIM);
#pragma unroll
        for (int j4 = 0; j4 < TDIM / 4; ++j4) {
            float4 t4 = __ldg(trow + j4);
            e2[2 * j4 + 0] = __floats2half2_rn(__expf(t4.x), __expf(t4.y));
            e2[2 * j4 + 1] = __floats2half2_rn(__expf(t4.z), __expf(t4.w));
        }
    }
    const float trans_bot = __ldg(trans + 1 * TDIM + i);  // trans[BOT=1, i]

    const float* emb = em + (size_t)b * (size_t)S * TDIM;
    const int*   Wb  = W  + (size_t)b * (size_t)S;

    // Preload word ids into SMEM (coalesced, one-time)
    for (int k = i; k < S; k += TDIM) w_sm[k] = Wb[k];

    // Raw state in HALF: t_h = exp(Beta - m_prev); Beta=0, m_{-1}=0 -> 1.
    __half t_h = __float2half_rn(1.0f);
    // Shift schedule (uniform fp32 registers).
    float m_prev = 0.0f, m_cur = 3.5f, m_nxt = 9.0f;
    float dN = m_prev - m_cur;                 // Delta of next executed step

    if (i == 0) { t0_sm[0] = 1.0f; t0_sm[1] = 1.0f; }

    // distance-2 prefetch of emission element (this row)
    float eA = emb[(size_t)(S - 1) * TDIM + i];
    float eB = emb[(size_t)(S - 2) * TDIM + i];

    __half preA = __float2half_rn(__expf(eA + dN));  // pre for 1st exec step

    int p = 0;  // parity over EXECUTED steps
    __syncthreads();    // also covers w_sm

    int wA = w_sm[S - 1];
    int wB = w_sm[S - 2];

    for (int r = S - 1; r >= 1; --r) {
        int rp = r - 2;
        rp = rp < 0 ? 0 : rp;               // r==1 prefetches row 0 (final)
        float eC = emb[(size_t)rp * TDIM + i];
        int   wC = w_sm[rp];

        if ((wA != 0) & (wA != 3)) {        // mask, uniform across block
            // ---- ON-PATH: u = t*pre (HMUL), STS.16, barrier ----
            u_sm[p][i] = __hmul(t_h, preA);
            __syncthreads();                // the ONLY barrier per step

            float T0 = t0_sm[p ^ 1];        // off-path broadcast

            __half2 acc[8];
#pragma unroll
            for (int k = 0; k < 8; ++k) acc[k] = __float2half2_rn(0.0f);

            const uint4* u4p = reinterpret_cast<const uint4*>(u_sm[p]);
#pragma unroll
            for (int k = 0; k < 16; ++k) {  // 16 x LDS.128 broadcast
                uint4 w = u4p[k];           // 8 halves = 4 half2
                __half2 h0 = *reinterpret_cast<__half2*>(&w.x);
                __half2 h1 = *reinterpret_cast<__half2*>(&w.y);
                __half2 h2 = *reinterpret_cast<__half2*>(&w.z);
                __half2 h3 = *reinterpret_cast<__half2*>(&w.w);
                acc[(4 * k + 0) & 7] = __hfma2(e2[4 * k + 0], h0, acc[(4 * k + 0) & 7]);
                acc[(4 * k + 1) & 7] = __hfma2(e2[4 * k + 1], h1, acc[(4 * k + 1) & 7]);
                acc[(4 * k + 2) & 7] = __hfma2(e2[4 * k + 2], h2, acc[(4 * k + 2) & 7]);
                acc[(4 * k + 3) & 7] = __hfma2(e2[4 * k + 3], h3, acc[(4 * k + 3) & 7]);
            }
            // 3-level half2 tree, then fold to scalar half (all fp16)
#pragma unroll
            for (int j = 0; j < 4; ++j) acc[j] = __hadd2(acc[j], acc[j + 4]);
#pragma unroll
            for (int j = 0; j < 2; ++j) acc[j] = __hadd2(acc[j], acc[j + 2]);
            acc[0] = __hadd2(acc[0], acc[1]);
            t_h = __hadd(__low2half(acc[0]), __high2half(acc[0]));

            if (i == 0) t0_sm[p] = __half2float(t_h);  // off-path publish

            // ---- OFF-PATH scalar m-chain (uniform, fp32) ----
            float m_new = m_prev + __logf(T0) + 10.85f;
            m_prev = m_cur;
            m_cur  = m_nxt;
            m_nxt  = m_new;
            dN = m_prev - m_cur;            // Delta of the next executed step
            p ^= 1;
        }

        // pre for row r-1, consumed next iteration (off-path MUFU + CVT)
        __half preB = __float2half_rn(__expf(eB + dN));

        eA = eB;  preA = preB;  wA = wB;
        eB = eC;  wB = wC;
    }

    // ---- logZ = lse_i( trans[BOT,i] + em[b,0,i] + m_last + log t_i ) ----
    float f = trans_bot + eA + m_prev + __logf(__half2float(t_h));

    float mv = f;
#pragma unroll
    for (int o = 16; o > 0; o >>= 1)
        mv = fmaxf(mv, __shfl_xor_sync(0xffffffffu, mv, o));
    if ((i & 31) == 0) red_sm[i >> 5] = mv;
    __syncthreads();
    float mm = fmaxf(fmaxf(red_sm[0], red_sm[1]), fmaxf(red_sm[2], red_sm[3]));

    float s = __expf(f - mm);
#pragma unroll
    for (int o = 16; o > 0; o >>= 1)
        s += __shfl_xor_sync(0xffffffffu, s, o);
    if ((i & 31) == 0) red_sm[4 + (i >> 5)] = s;
    __syncthreads();

    if (i == 0) {
        float tot = (red_sm[4] + red_sm[5]) + (red_sm[6] + red_sm[7]);
        out[b] = mm + __logf(tot);
    }
}

extern "C" void kernel_launch(void* const* d_in, const int* in_sizes, int n_in,
                              void* d_out, int out_size)
{
    const int*   W     = (const int*)d_in[0];
    const float* em    = (const float*)d_in[1];
    const float* trans = (const float*)d_in[2];
    float*       out   = (float*)d_out;

    const int B = out_size;            // 64
    const int S = in_sizes[0] / B;     // 1024

    crf_logz_kernel<<<B, TDIM, S * (int)sizeof(int)>>>(W, em, trans, out, S);
}